// round 10
// baseline (speedup 1.0000x reference)
#include <cuda_runtime.h>
#include <stdint.h>

// image: [16, 3, 1024, 1024] fp32 ; camera_index: [16] int32
// weight/bias: [34, 3] fp32
// out = image * weight[cam[b], c] + bias[cam[b], c]
//
// HBM-bound stream at ~90% of the mixed R/W HBM3e ceiling. This round:
// sm_10x 256-bit vector ld/st (LDG.E.256 / STG.E.256) — halves memory
// instruction count at identical per-thread traffic (2x float8 vs 4x float4).

static constexpr int B  = 16;
static constexpr int C  = 3;
static constexpr int HW8 = (1024 * 1024) / 8;    // 131072 float8 per plane

static constexpr int TPB = 256;
static constexpr int V_PER_THREAD = 2;           // 2 x 32B = 64B/thread loaded
static constexpr int BLK_X = HW8 / (TPB * V_PER_THREAD);   // 256 blocks/plane

struct alignas(32) f8 { float v[8]; };

__device__ __forceinline__ f8 ldg256(const f8* p) {
    f8 r;
    asm volatile("ld.global.nc.v8.f32 {%0,%1,%2,%3,%4,%5,%6,%7}, [%8];"
                 : "=f"(r.v[0]), "=f"(r.v[1]), "=f"(r.v[2]), "=f"(r.v[3]),
                   "=f"(r.v[4]), "=f"(r.v[5]), "=f"(r.v[6]), "=f"(r.v[7])
                 : "l"(p));
    return r;
}

__device__ __forceinline__ void stg256(f8* p, const f8& x) {
    asm volatile("st.global.v8.f32 [%0], {%1,%2,%3,%4,%5,%6,%7,%8};"
                 :: "l"(p),
                    "f"(x.v[0]), "f"(x.v[1]), "f"(x.v[2]), "f"(x.v[3]),
                    "f"(x.v[4]), "f"(x.v[5]), "f"(x.v[6]), "f"(x.v[7])
                 : "memory");
}

__global__ __launch_bounds__(TPB) void colorcal_kernel(
    const f8* __restrict__ img,
    const int* __restrict__ cam_idx,
    const float* __restrict__ weight,
    const float* __restrict__ bias,
    f8* __restrict__ out)
{
    const int plane = blockIdx.y;                // 0..47
    const int b = plane / C;
    const int c = plane - b * C;

    const int cam = cam_idx[b];                  // uniform per block
    const float s = __ldg(&weight[cam * C + c]);
    const float t = __ldg(&bias[cam * C + c]);

    const f8* __restrict__ src = img + (size_t)plane * HW8;
    f8* __restrict__ dst       = out + (size_t)plane * HW8;

    const int base = blockIdx.x * TPB + threadIdx.x;
    const int stride = BLK_X * TPB;              // 65536 f8

    // Front-batch both 256-bit loads, then compute+store.
    f8 x[V_PER_THREAD];
    #pragma unroll
    for (int v = 0; v < V_PER_THREAD; v++)
        x[v] = ldg256(&src[base + v * stride]);

    #pragma unroll
    for (int v = 0; v < V_PER_THREAD; v++) {
        f8 y;
        #pragma unroll
        for (int k = 0; k < 8; k++)
            y.v[k] = fmaf(x[v].v[k], s, t);
        stg256(&dst[base + v * stride], y);
    }
}

extern "C" void kernel_launch(void* const* d_in, const int* in_sizes, int n_in,
                              void* d_out, int out_size)
{
    const f8*    img = (const f8*)d_in[0];
    const int*   cam = (const int*)d_in[1];
    const float* w   = (const float*)d_in[2];
    const float* bia = (const float*)d_in[3];
    f8*          o   = (f8*)d_out;

    dim3 grid(BLK_X, B * C, 1);
    colorcal_kernel<<<grid, TPB>>>(img, cam, w, bia, o);
}